// round 1
// baseline (speedup 1.0000x reference)
#include <cuda_runtime.h>
#include <cstdint>

// TopKRouter: logits = x @ W^T + b ; top-2 ; softmax(top2 vals)
// x: [B*S, 2048] f32, W: [64, 2048] f32, b: [64] f32
// out: [n_tokens*2] gates f32 followed by [n_tokens*2] indices (as f32)

#define D_DIM     2048
#define NEXP      64
#define TOK_CTA   64
#define KC        64           // k-chunk staged in smem
#define NCH       (D_DIM / KC) // 32 chunks
#define STRIDE    68           // floats per smem row (64 data + 4 pad), 16B-aligned rows
#define LG_STRIDE 65           // epilogue logits row stride (conflict-free scalar)

__global__ __launch_bounds__(256, 2)
void topk_router_kernel(const float* __restrict__ x,
                        const float* __restrict__ W,
                        const float* __restrict__ b,
                        float* __restrict__ out,
                        int n_tokens)
{
    __shared__ __align__(16) float xs[TOK_CTA * STRIDE];
    __shared__ __align__(16) float ws[NEXP * STRIDE];

    const int tid  = threadIdx.x;
    const int tok0 = blockIdx.x * TOK_CTA;

    // thread tile: 4 tokens x 4 experts. 16 expert-groups x 16 token-groups.
    const int exg  = tid & 15;   // expert group: experts 4*exg .. 4*exg+3
    const int tokg = tid >> 4;   // token group : tokens  4*tokg .. 4*tokg+3

    // packed f32x2 accumulators: acc[i][j] holds (sum_even, sum_odd) over k-pairs
    unsigned long long acc[4][4];
#pragma unroll
    for (int i = 0; i < 4; i++)
#pragma unroll
        for (int j = 0; j < 4; j++)
            acc[i][j] = 0ull;   // packed (0.0f, 0.0f)

    const int xswz = tokg & 7;
    const int wswz = exg & 7;
    int xbase[4], wbase[4];
#pragma unroll
    for (int i = 0; i < 4; i++) xbase[i] = (4 * tokg + i) * STRIDE;
#pragma unroll
    for (int j = 0; j < 4; j++) wbase[j] = (4 * exg + j) * STRIDE;

    // cooperative-load mapping: each thread moves 4 float4 per tile
    // f = p*256 + tid ; row = f>>4 ; c = f&15 (16 float4 per 64-float row)
    for (int ch = 0; ch < NCH; ch++) {
        const int kc = ch * KC;

        // ---- stage x tile [64 tok x 64 k] and W tile [64 exp x 64 k] ----
#pragma unroll
        for (int p = 0; p < 4; p++) {
            int f   = p * 256 + tid;
            int row = f >> 4;
            int c   = f & 15;
            int sw  = (c ^ ((row >> 2) & 7)) << 2;

            float4 xv = *reinterpret_cast<const float4*>(
                &x[(size_t)(tok0 + row) * D_DIM + kc + (c << 2)]);
            *reinterpret_cast<float4*>(&xs[row * STRIDE + sw]) = xv;

            float4 wv = *reinterpret_cast<const float4*>(
                &W[(size_t)row * D_DIM + kc + (c << 2)]);
            *reinterpret_cast<float4*>(&ws[row * STRIDE + sw]) = wv;
        }
        __syncthreads();

        // ---- compute: 16 k4-steps of 4 k's each ----
#pragma unroll 4
        for (int k4 = 0; k4 < 16; k4++) {
            const int xo = (k4 ^ xswz) << 2;
            const int wo = (k4 ^ wswz) << 2;

            ulonglong2 xv[4], wv[4];
#pragma unroll
            for (int i = 0; i < 4; i++)
                xv[i] = *reinterpret_cast<const ulonglong2*>(&xs[xbase[i] + xo]);
#pragma unroll
            for (int j = 0; j < 4; j++)
                wv[j] = *reinterpret_cast<const ulonglong2*>(&ws[wbase[j] + wo]);

#pragma unroll
            for (int i = 0; i < 4; i++) {
#pragma unroll
                for (int j = 0; j < 4; j++) {
                    asm("fma.rn.f32x2 %0, %1, %2, %0;"
                        : "+l"(acc[i][j]) : "l"(xv[i].x), "l"(wv[j].x));
                    asm("fma.rn.f32x2 %0, %1, %2, %0;"
                        : "+l"(acc[i][j]) : "l"(xv[i].y), "l"(wv[j].y));
                }
            }
        }
        __syncthreads();
    }

    // ---- epilogue: logits to smem (reuse xs), add bias ----
    float* lg = xs;  // needs 64*65 = 4160 floats <= 64*68
    float bj[4];
#pragma unroll
    for (int j = 0; j < 4; j++) bj[j] = __ldg(&b[4 * exg + j]);

#pragma unroll
    for (int i = 0; i < 4; i++) {
#pragma unroll
        for (int j = 0; j < 4; j++) {
            float2 f2 = *reinterpret_cast<float2*>(&acc[i][j]);
            lg[(4 * tokg + i) * LG_STRIDE + 4 * exg + j] = f2.x + f2.y + bj[j];
        }
    }
    __syncthreads();

    // ---- top-2 + softmax: one thread per token ----
    if (tid < TOK_CTA) {
        const float* row = &lg[tid * LG_STRIDE];
        float v1 = row[0], v2 = -3.402823466e+38f;
        int   i1 = 0,      i2 = 0;
#pragma unroll
        for (int e = 1; e < NEXP; e++) {
            float v = row[e];
            if (v > v1)      { v2 = v1; i2 = i1; v1 = v; i1 = e; }
            else if (v > v2) { v2 = v;  i2 = e; }
        }
        float e2 = expf(v2 - v1);
        float inv = 1.0f / (1.0f + e2);
        float g1 = inv;
        float g2 = e2 * inv;

        const int g = tok0 + tid;
        out[2 * g + 0] = g1;
        out[2 * g + 1] = g2;
        const int idx_base = n_tokens * 2;
        out[idx_base + 2 * g + 0] = (float)i1;
        out[idx_base + 2 * g + 1] = (float)i2;
    }
}

extern "C" void kernel_launch(void* const* d_in, const int* in_sizes, int n_in,
                              void* d_out, int out_size)
{
    const float* x = (const float*)d_in[0];
    const float* W = (const float*)d_in[1];
    const float* b = (const float*)d_in[2];
    float* out = (float*)d_out;

    const int n_tokens = in_sizes[0] / D_DIM;  // 16384
    const int grid = n_tokens / TOK_CTA;       // 256

    topk_router_kernel<<<grid, 256>>>(x, W, b, out, n_tokens);
}

// round 3
// speedup vs baseline: 1.9674x; 1.9674x over previous
#include <cuda_runtime.h>
#include <cuda_fp16.h>
#include <cstdint>

// ============================================================
// TopKRouter via mma.sync (HMMA fp16, 2-split emulated fp32):
//   logits = x @ W^T + b ; top-2 ; softmax(top2)
// x:[16384,2048] f32  W:[64,2048] f32  b:[64] f32
// out: [n*2] gates f32, then [n*2] indices as f32
// ============================================================

#define D_DIM  2048
#define NEXP   64
#define M_CTA  64
#define NCH    32          // k-chunks of 64
#define NTHREADS 128

// smem layout (bytes)
#define ABYTES   8192                 // 64 rows x 128B (64 halves)
#define AH0(p)   (1024 + (p) * 32768)
#define AH1(p)   (AH0(p) + 8192)
#define BW0(p)   (AH0(p) + 16384)
#define BW1(p)   (AH0(p) + 24576)
#define LG_OFF   1024                 // epilogue logits (reuses buf0)
#define SMEM_TOTAL (1024 + 65536)

#define LGS 65                        // logits row stride (floats)
#define SW16(row, c) ((row) * 128 + ((((c) ^ ((row) & 7))) << 4))

// W fp16 splits (prologue output): w0 = fp16(w), w1 = fp16((w - w0) * 2048)
__device__ __align__(16) __half w0g[NEXP * D_DIM];
__device__ __align__(16) __half w1g[NEXP * D_DIM];

// ---------------- prologue: split W ----------------
__global__ void wconv(const float* __restrict__ W) {
    int i = blockIdx.x * blockDim.x + threadIdx.x;
    float w = W[i];
    __half h0 = __float2half_rn(w);
    float  r  = w - __half2float(h0);          // exact (Sterbenz)
    __half h1 = __float2half_rn(r * 2048.0f);  // scaled to avoid subnormals
    w0g[i] = h0;
    w1g[i] = h1;
}

// ---------------- asm helpers ----------------
__device__ __forceinline__ uint32_t smem_u32(const void* p) {
    uint32_t a;
    asm("{ .reg .u64 t; cvta.to.shared.u64 t, %1; cvt.u32.u64 %0, t; }"
        : "=r"(a) : "l"(p));
    return a;
}
__device__ __forceinline__ void ldsm4(uint32_t* r, uint32_t addr) {
    asm volatile("ldmatrix.sync.aligned.m8n8.x4.shared.b16 {%0,%1,%2,%3}, [%4];"
                 : "=r"(r[0]), "=r"(r[1]), "=r"(r[2]), "=r"(r[3]) : "r"(addr));
}
__device__ __forceinline__ void mma16816(float* d, const uint32_t* a, const uint32_t* b) {
    asm volatile("mma.sync.aligned.m16n8k16.row.col.f32.f16.f16.f32 "
                 "{%0,%1,%2,%3}, {%4,%5,%6,%7}, {%8,%9}, {%0,%1,%2,%3};"
                 : "+f"(d[0]), "+f"(d[1]), "+f"(d[2]), "+f"(d[3])
                 : "r"(a[0]), "r"(a[1]), "r"(a[2]), "r"(a[3]), "r"(b[0]), "r"(b[1]));
}
__device__ __forceinline__ void cp16(uint32_t saddr, const void* gaddr) {
    asm volatile("cp.async.cg.shared.global [%0], [%1], 16;"
                 :: "r"(saddr), "l"(gaddr));
}
#define CP_COMMIT() asm volatile("cp.async.commit_group;" ::: "memory")
#define CP_WAIT(N)  asm volatile("cp.async.wait_group %0;" :: "n"(N) : "memory")
#define STS64(addr, u0, u1) \
    asm volatile("st.shared.v2.b32 [%0], {%1,%2};" :: "r"(addr), "r"(u0), "r"(u1) : "memory")

// ---------------- main kernel ----------------
__global__ __launch_bounds__(NTHREADS, 2)
void router_main(const float* __restrict__ x, const float* __restrict__ b,
                 float* __restrict__ out, int n_tokens)
{
    extern __shared__ __align__(1024) char smem[];
    const uint32_t sb = smem_u32(smem);
    const int tid  = threadIdx.x;
    const int wid  = tid >> 5;
    const int lane = tid & 31;
    const int tok0 = blockIdx.x * M_CTA;

    // bias -> smem[0..255]
    if (tid < NEXP) reinterpret_cast<float*>(smem)[tid] = b[tid];

    // ---- x loader mapping: f4 linear L = tid + 128*i ; r = L>>4 ; c = L&15 ----
    const int xr = tid >> 4;          // base row (rows xr + 8i)
    const int xc = tid & 15;          // f4 column within 64-float chunk row
    const float4* xp = reinterpret_cast<const float4*>(x)
                       + (size_t)(tok0 + xr) * (D_DIM / 4) + xc;

    // ---- W cp.async mapping: thread t -> split (t&1), row (t>>1), 8x16B ----
    const int wsp  = tid & 1;
    const int wrow = tid >> 1;
    const char* wg = reinterpret_cast<const char*>(wsp ? w1g : w0g) + wrow * (D_DIM * 2);
    const uint32_t wdstb = sb + (wsp ? (BW1(0) - AH0(0)) : (BW0(0) - AH0(0)));

    // prefetch chunk 0
    float4 xv[8];
#pragma unroll
    for (int i = 0; i < 8; i++) xv[i] = xp[i * 8 * (D_DIM / 4)];
#pragma unroll
    for (int c = 0; c < 8; c++)
        cp16(wdstb + AH0(0) + SW16(wrow, c), wg + c * 16);
    CP_COMMIT();

    // ---- compute setup ----
    const int m0 = (wid & 1) * 32;
    const int n0 = (wid >> 1) * 32;
    float acc0[2][4][4], acc1[2][4][4];
#pragma unroll
    for (int mi = 0; mi < 2; mi++)
#pragma unroll
        for (int ng = 0; ng < 4; ng++)
#pragma unroll
            for (int q = 0; q < 4; q++) { acc0[mi][ng][q] = 0.f; acc1[mi][ng][q] = 0.f; }

    // ldmatrix lane addressing (row, 16B-chunk) precompute
    const int rowA  = m0 + (lane & 15);
    const int cAoff = lane >> 4;                          // 0/1 -> k0/k8
    const int rowB  = n0 + (lane & 7) + ((lane >> 4) << 3);
    const int cBoff = (lane >> 3) & 1;

    for (int ch = 0; ch < NCH; ch++) {
        const int p = ch & 1;

        // ---- convert x chunk -> fp16 split tiles (STS.64 each) ----
#pragma unroll
        for (int i = 0; i < 8; i++) {
            const int r  = xr + 8 * i;
            const int cc = xc >> 1;
            const int h8 = (xc & 1) * 8;
            float4 v = xv[i];
            __half2 h0a = __float22half2_rn(make_float2(v.x, v.y));
            __half2 h0b = __float22half2_rn(make_float2(v.z, v.w));
            float2 f0a = __half22float2(h0a);
            float2 f0b = __half22float2(h0b);
            __half2 h1a = __float22half2_rn(make_float2(v.x - f0a.x, v.y - f0a.y));
            __half2 h1b = __float22half2_rn(make_float2(v.z - f0b.x, v.w - f0b.y));
            uint32_t base = sb + SW16(r, cc) + h8;
            STS64(base + AH0(p), *reinterpret_cast<uint32_t*>(&h0a),
                                 *reinterpret_cast<uint32_t*>(&h0b));
            STS64(base + AH1(p), *reinterpret_cast<uint32_t*>(&h1a),
                                 *reinterpret_cast<uint32_t*>(&h1b));
        }

        if (ch + 1 < NCH) {
            // prefetch next x chunk into regs
#pragma unroll
            for (int i = 0; i < 8; i++)
                xv[i] = xp[(ch + 1) * 16 + i * 8 * (D_DIM / 4)];
            // cp.async next W chunk into other buffer
#pragma unroll
            for (int c = 0; c < 8; c++)
                cp16(wdstb + AH0(p ^ 1) + SW16(wrow, c), wg + (ch + 1) * 128 + c * 16);
            CP_COMMIT();
            CP_WAIT(1);   // current chunk's W group done
        } else {
            CP_WAIT(0);
        }
        __syncthreads();

        // ---- compute on buffer p ----
#pragma unroll
        for (int kk = 0; kk < 4; kk++) {
            uint32_t a0f[2][4], a1f[2][4], b0f[2][4], b1f[2][4];
            const int cA = kk * 2 + cAoff;
            const int cB = kk * 2 + cBoff;
#pragma unroll
            for (int mi = 0; mi < 2; mi++) {
                uint32_t ad = sb + AH0(p) + SW16(rowA + mi * 16, cA);
                ldsm4(a0f[mi], ad);
                ldsm4(a1f[mi], ad + ABYTES);   // AH1 directly after AH0
            }
#pragma unroll
            for (int ni2 = 0; ni2 < 2; ni2++) {
                uint32_t bd = sb + BW0(p) + SW16(rowB + ni2 * 16, cB);
                ldsm4(b0f[ni2], bd);
                ldsm4(b1f[ni2], bd + ABYTES);  // BW1 after BW0
            }
#pragma unroll
            for (int mi = 0; mi < 2; mi++) {
#pragma unroll
                for (int ng = 0; ng < 4; ng++) {
                    const uint32_t* B0 = &b0f[ng >> 1][(ng & 1) * 2];
                    const uint32_t* B1 = &b1f[ng >> 1][(ng & 1) * 2];
                    mma16816(acc0[mi][ng], a0f[mi], B0);
                    mma16816(acc0[mi][ng], a1f[mi], B0);
                    mma16816(acc1[mi][ng], a0f[mi], B1);
                }
            }
        }
        __syncthreads();
    }

    // ---- epilogue: combine splits, write logits to smem ----
    float* lg = reinterpret_cast<float*>(smem + LG_OFF);
    const float S = 4.8828125e-4f;  // 2^-11
#pragma unroll
    for (int mi = 0; mi < 2; mi++) {
#pragma unroll
        for (int ng = 0; ng < 4; ng++) {
            int row = m0 + mi * 16 + (lane >> 2);
            int col = n0 + ng * 8 + 2 * (lane & 3);
            lg[row * LGS + col]           = acc0[mi][ng][0] + S * acc1[mi][ng][0];
            lg[row * LGS + col + 1]       = acc0[mi][ng][1] + S * acc1[mi][ng][1];
            lg[(row + 8) * LGS + col]     = acc0[mi][ng][2] + S * acc1[mi][ng][2];
            lg[(row + 8) * LGS + col + 1] = acc0[mi][ng][3] + S * acc1[mi][ng][3];
        }
    }
    __syncthreads();

    // ---- top-2 + softmax, one thread per token ----
    if (tid < M_CTA) {
        const float* row = &lg[tid * LGS];
        const float* bs  = reinterpret_cast<const float*>(smem);
        float v1 = -3.402823466e+38f, v2 = -3.402823466e+38f;
        int i1 = 0, i2 = 0;
#pragma unroll
        for (int e = 0; e < NEXP; e++) {
            float v = row[e] + bs[e];
            if (v > v1)      { v2 = v1; i2 = i1; v1 = v; i1 = e; }
            else if (v > v2) { v2 = v;  i2 = e; }
        }
        float e2  = expf(v2 - v1);
        float inv = 1.0f / (1.0f + e2);
        const int g = tok0 + tid;
        out[2 * g + 0] = inv;
        out[2 * g + 1] = e2 * inv;
        out[2 * n_tokens + 2 * g + 0] = (float)i1;
        out[2 * n_tokens + 2 * g + 1] = (float)i2;
    }
}

// ---------------- launch ----------------
extern "C" void kernel_launch(void* const* d_in, const int* in_sizes, int n_in,
                              void* d_out, int out_size)
{
    const float* x = (const float*)d_in[0];
    const float* W = (const float*)d_in[1];
    const float* b = (const float*)d_in[2];
    float* out = (float*)d_out;

    const int n_tokens = in_sizes[0] / D_DIM;   // 16384
    const int grid = n_tokens / M_CTA;          // 256

    cudaFuncSetAttribute(router_main, cudaFuncAttributeMaxDynamicSharedMemorySize, SMEM_TOTAL);

    wconv<<<NEXP * D_DIM / 256, 256>>>(W);
    router_main<<<grid, NTHREADS, SMEM_TOTAL>>>(x, b, out, n_tokens);
}